// round 7
// baseline (speedup 1.0000x reference)
#include <cuda_runtime.h>
#include <math.h>

#define B_ROWS 16384
#define C_CLS  1000
#define NNODES 4096
#define NEDGES 131072

#define NBLK   512                  // one resident wave; 8 warps/block
#define NWARP  (NBLK * 8)           // 4096: divides rows (x4) and edge chunks (x1)

__device__ float2 g_partials[NBLK];
__device__ unsigned int g_ticket = 0;

__global__ __launch_bounds__(256, 4) void fused_kernel(const float* __restrict__ outputs,
                                                       const int* __restrict__ targets,
                                                       const float* __restrict__ P,
                                                       const int* __restrict__ src,
                                                       const int* __restrict__ dst,
                                                       float* __restrict__ out) {
    const int t = threadIdx.x;
    const int lane = t & 31;
    const int warp = t >> 5;
    const int gw = blockIdx.x * 8 + warp;   // 0..4095

    const float TWO_PI_F = 6.2831853071795864769f;
    const float PI_F     = 3.1415926535897932385f;

    // ---- issue scattered edge gathers early (consumed at the very end) ----
    const int e  = gw * 32 + lane;
    const int si = __ldg(&src[e]);
    const int di = __ldg(&dst[e]);
    const float pa = __ldg(&P[(size_t)si * NNODES + di]);
    const float pb = __ldg(&P[(size_t)di * NNODES + si]);

    // ---- issue all 4 target-logit gathers early ----
    const float* rowp[4];
    float xt[4];
    #pragma unroll
    for (int j = 0; j < 4; j++) {
        const int row = gw + j * NWARP;
        rowp[j] = outputs + (size_t)row * C_CLS;
        xt[j] = __ldg(&rowp[j][__ldg(&targets[row])]);
    }

    // ---- 4 CE rows, processed as 2 pairs with independent sums ----
    float ce_acc = 0.0f;
    #pragma unroll
    for (int p = 0; p < 2; p++) {
        const float4* __restrict__ r0 = reinterpret_cast<const float4*>(rowp[2 * p]);
        const float4* __restrict__ r1 = reinterpret_cast<const float4*>(rowp[2 * p + 1]);

        float s0 = 0.0f, s1 = 0.0f;
        #pragma unroll
        for (int k = 0; k < 7; k++) {
            float4 va = r0[lane + 32 * k];
            float4 vb = r1[lane + 32 * k];
            s0 += __expf(va.x) + __expf(va.y) + __expf(va.z) + __expf(va.w);
            s1 += __expf(vb.x) + __expf(vb.y) + __expf(vb.z) + __expf(vb.w);
        }
        if (lane < 26) {                       // 250 = 7*32 + 26
            float4 va = r0[lane + 224];
            float4 vb = r1[lane + 224];
            s0 += __expf(va.x) + __expf(va.y) + __expf(va.z) + __expf(va.w);
            s1 += __expf(vb.x) + __expf(vb.y) + __expf(vb.z) + __expf(vb.w);
        }

        // two independent shfl chains -> interleaved issue, half the bubble
        #pragma unroll
        for (int off = 16; off > 0; off >>= 1) {
            s0 += __shfl_xor_sync(0xFFFFFFFFu, s0, off);
            s1 += __shfl_xor_sync(0xFFFFFFFFu, s1, off);
        }
        ce_acc += (__logf(s0) - xt[2 * p]) + (__logf(s1) - xt[2 * p + 1]);
    }

    // ---- resonance from the early gathers ----
    float d = fabsf(pa - pb);
    d = fmodf(d, TWO_PI_F);
    if (d > PI_F) d = TWO_PI_F - d;
    float res_acc = d;
    #pragma unroll
    for (int off = 16; off > 0; off >>= 1)
        res_acc += __shfl_xor_sync(0xFFFFFFFFu, res_acc, off);

    // ---- block reduce + last-block finalize ----
    __shared__ float s_ce[8], s_res[8];
    __shared__ bool is_last;
    if (lane == 0) { s_ce[warp] = ce_acc; s_res[warp] = res_acc; }
    __syncthreads();

    if (t == 0) {
        float ce = 0.0f, rs = 0.0f;
        #pragma unroll
        for (int w = 0; w < 8; w++) { ce += s_ce[w]; rs += s_res[w]; }
        g_partials[blockIdx.x] = make_float2(ce, rs);
        __threadfence();
        unsigned int ticket = atomicAdd(&g_ticket, 1u);
        is_last = (ticket == NBLK - 1);
    }
    __syncthreads();

    if (is_last) {
        float ce = 0.0f, rs = 0.0f;
        for (int i = t; i < NBLK; i += 256) {
            float2 p = g_partials[i];
            ce += p.x; rs += p.y;
        }
        float vloc = ce * (1.0f / B_ROWS) + 0.1f * rs * (1.0f / NEDGES);

        __shared__ float red[256];
        red[t] = vloc;
        __syncthreads();
        #pragma unroll
        for (int stride = 128; stride > 0; stride >>= 1) {
            if (t < stride) red[t] += red[t + stride];
            __syncthreads();
        }
        if (t == 0) {
            out[0] = red[0];
            g_ticket = 0;     // reset for next graph replay
        }
    }
}

extern "C" void kernel_launch(void* const* d_in, const int* in_sizes, int n_in,
                              void* d_out, int out_size) {
    const float* outputs = (const float*)d_in[0];
    const int*   targets = (const int*)d_in[1];
    const float* phase   = (const float*)d_in[2];
    const int*   esrc    = (const int*)d_in[3];
    const int*   edst    = (const int*)d_in[4];
    float* out = (float*)d_out;

    fused_kernel<<<NBLK, 256>>>(outputs, targets, phase, esrc, edst, out);
}